// round 2
// baseline (speedup 1.0000x reference)
#include <cuda_runtime.h>
#include <cstdint>

#define BATCH    64
#define SEQ      8192
#define RDIM     80
#define NTAPS    5
#define MAXD     168
#define RING     169          // MAXD+1: write slot disjoint from all read slots
#define NTHREADS 320          // lane map: jh = tid&3 (j-quarter), i = tid>>2
#define JSLICE   20
#define NPAIR    10           // f32x2 pairs per tap per thread

typedef unsigned long long u64;

__device__ __forceinline__ u64 ffma2(u64 a, u64 b, u64 c) {
    u64 d;
    asm("fma.rn.f32x2 %0, %1, %2, %3;" : "=l"(d) : "l"(a), "l"(b), "l"(c));
    return d;
}

__device__ __forceinline__ float2 unpack2(u64 v) {
    unsigned lo, hi;
    asm("mov.b64 {%0, %1}, %2;" : "=r"(lo), "=r"(hi) : "l"(v));
    float2 r;
    r.x = __uint_as_float(lo);
    r.y = __uint_as_float(hi);
    return r;
}

__device__ __forceinline__ float fast_tanh(float v) {
    v = fminf(fmaxf(v, -15.0f), 15.0f);
    float u = __expf(-2.0f * v);                 // MUFU.EX2 path
    return __fdividef(1.0f - u, 1.0f + u);       // MUFU.RCP path
}

__global__ __launch_bounds__(NTHREADS, 1)
void reservoir_kernel(const float* __restrict__ x,
                      const float* __restrict__ Win,
                      const float* __restrict__ Wfb,
                      const float* __restrict__ bias,
                      float* __restrict__ out)
{
    extern __shared__ float sm[];
    float* Hring = sm;                     // [RING][RDIM] = 13520 f
    float* xs    = Hring + RING * RDIM;    // [SEQ]        = 8192 f

    const int b   = blockIdx.x;
    const int tid = threadIdx.x;
    const int jh  = tid & 3;               // j-quarter 0..3 (adjacent lanes)
    const int i   = tid >> 2;              // output index 0..79

    // Zero the state ring (pre-t=0 states are zero)
    for (int idx = tid; idx < RING * RDIM; idx += NTHREADS) Hring[idx] = 0.0f;

    // Stage this batch's input sequence (INPUT_DIM == 1)
    const float* xb = x + (size_t)b * SEQ;
    for (int idx = tid; idx < SEQ; idx += NTHREADS) xs[idx] = xb[idx];

    // W_fb slice in registers as f32x2 pairs:
    // feedback[i] = sum_k sum_j delayed[k][j] * Wfb[k][i][j]
    u64 Wp[NTAPS][NPAIR];
#pragma unroll
    for (int k = 0; k < NTAPS; k++) {
        const float* wrow = Wfb + ((size_t)k * RDIM + i) * RDIM + jh * JSLICE;
#pragma unroll
        for (int p = 0; p < NPAIR; p++) {
            unsigned lo = __float_as_uint(wrow[2 * p]);
            unsigned hi = __float_as_uint(wrow[2 * p + 1]);
            Wp[k][p] = ((u64)hi << 32) | (u64)lo;
        }
    }

    const float win_i  = Win[i];
    const float bias_i = bias[i];
    float h_i = 0.0f;

    float* outb = out + (size_t)b * SEQ * RDIM;

    // Ring offsets: write slot w = t mod 169; read slot r_k = (t - tau_k) mod 169.
    // At t=0: w=0, r = 169 - tau.
    int w  = 0;
    int r0 = RING - 1;    // tau 1
    int r1 = RING - 4;    // tau 4
    int r2 = RING - 24;   // tau 24
    int r3 = RING - 96;   // tau 96
    int r4 = RING - 168;  // tau 168

    __syncthreads();

    for (int t = 0; t < SEQ; ++t) {
        const float x_t = xs[t];

        u64 a0 = 0ull, a1 = 0ull, a2 = 0ull, a3 = 0ull;
        int slot[NTAPS] = { r0, r1, r2, r3, r4 };
#pragma unroll
        for (int k = 0; k < NTAPS; k++) {
            // 4 distinct 16B addresses per warp (one per jh), 8-way broadcast,
            // different banks -> conflict-free single-phase LDS.128.
            const ulonglong2* hv = reinterpret_cast<const ulonglong2*>(
                Hring + slot[k] * RDIM + jh * JSLICE);
            ulonglong2 h01 = hv[0];
            ulonglong2 h23 = hv[1];
            ulonglong2 h45 = hv[2];
            ulonglong2 h67 = hv[3];
            ulonglong2 h89 = hv[4];
            a0 = ffma2(h01.x, Wp[k][0], a0);
            a1 = ffma2(h01.y, Wp[k][1], a1);
            a2 = ffma2(h23.x, Wp[k][2], a2);
            a3 = ffma2(h23.y, Wp[k][3], a3);
            a0 = ffma2(h45.x, Wp[k][4], a0);
            a1 = ffma2(h45.y, Wp[k][5], a1);
            a2 = ffma2(h67.x, Wp[k][6], a2);
            a3 = ffma2(h67.y, Wp[k][7], a3);
            a0 = ffma2(h89.x, Wp[k][8], a0);
            a1 = ffma2(h89.y, Wp[k][9], a1);
        }

        float2 f0 = unpack2(a0);
        float2 f1 = unpack2(a1);
        float2 f2 = unpack2(a2);
        float2 f3 = unpack2(a3);
        float f = ((f0.x + f0.y) + (f1.x + f1.y)) +
                  ((f2.x + f2.y) + (f3.x + f3.y));

        // Butterfly over the 4 j-quarter lanes of this i
        f += __shfl_xor_sync(0xffffffffu, f, 1);
        f += __shfl_xor_sync(0xffffffffu, f, 2);

        // All 4 lanes compute the update redundantly (identical bits)
        float val = fmaf(x_t, win_i, f + bias_i);
        h_i = 0.7f * h_i + 0.3f * fast_tanh(val);

        if (jh == 0) {
            Hring[w * RDIM + i] = h_i;            // 8 consecutive floats/warp
            outb[(size_t)t * RDIM + i] = h_i;     // coalesced 32B/warp
        }

        // advance ring offsets (mod 169)
        ++w;  if (w  == RING) w  = 0;
        ++r0; if (r0 == RING) r0 = 0;
        ++r1; if (r1 == RING) r1 = 0;
        ++r2; if (r2 == RING) r2 = 0;
        ++r3; if (r3 == RING) r3 = 0;
        ++r4; if (r4 == RING) r4 = 0;

        // Single barrier: makes write(t) visible to reads(t+1).
        // (Write slot is disjoint from all read slots within a step: RING=169.)
        __syncthreads();
    }
}

extern "C" void kernel_launch(void* const* d_in, const int* in_sizes, int n_in,
                              void* d_out, int out_size)
{
    const float* x    = (const float*)d_in[0];  // [64, 8192, 1]
    const float* Win  = (const float*)d_in[1];  // [80, 1]
    const float* Wfb  = (const float*)d_in[2];  // [5, 80, 80]
    const float* bias = (const float*)d_in[3];  // [80]
    float* out = (float*)d_out;                 // [64, 8192, 80]

    const int smem_bytes = (RING * RDIM + SEQ) * sizeof(float);
    cudaFuncSetAttribute(reservoir_kernel,
                         cudaFuncAttributeMaxDynamicSharedMemorySize, smem_bytes);

    reservoir_kernel<<<BATCH, NTHREADS, smem_bytes>>>(x, Win, Wfb, bias, out);
}

// round 3
// speedup vs baseline: 1.6309x; 1.6309x over previous
#include <cuda_runtime.h>
#include <cstdint>

#define BATCH    64
#define SEQ      8192
#define RDIM     80
#define NTAPS    5
#define MAXD     168
#define RING     169          // MAXD+1: write slot disjoint from all read slots
#define NTHREADS 320          // i = tid % 80, jh = tid / 80
#define JSLICE   20
#define NPAIR    10           // f32x2 pairs per tap per thread

typedef unsigned long long u64;

__device__ __forceinline__ u64 ffma2(u64 a, u64 b, u64 c) {
    u64 d;
    asm("fma.rn.f32x2 %0, %1, %2, %3;" : "=l"(d) : "l"(a), "l"(b), "l"(c));
    return d;
}

__device__ __forceinline__ float2 unpack2(u64 v) {
    unsigned lo, hi;
    asm("mov.b64 {%0, %1}, %2;" : "=r"(lo), "=r"(hi) : "l"(v));
    float2 r;
    r.x = __uint_as_float(lo);
    r.y = __uint_as_float(hi);
    return r;
}

__device__ __forceinline__ float fast_tanh(float v) {
    v = fminf(fmaxf(v, -15.0f), 15.0f);
    float u = __expf(-2.0f * v);                 // MUFU.EX2 path
    return __fdividef(1.0f - u, 1.0f + u);       // MUFU.RCP path
}

// Accumulate one tap row (20 floats starting at hrow) against Wp[k][*]
#define TAP_ACC(k, hrow)                                                  \
    do {                                                                  \
        const ulonglong2* hv = reinterpret_cast<const ulonglong2*>(hrow); \
        ulonglong2 h01 = hv[0];                                           \
        ulonglong2 h23 = hv[1];                                           \
        ulonglong2 h45 = hv[2];                                           \
        ulonglong2 h67 = hv[3];                                           \
        ulonglong2 h89 = hv[4];                                           \
        a0 = ffma2(h01.x, Wp[k][0], a0);                                  \
        a1 = ffma2(h01.y, Wp[k][1], a1);                                  \
        a2 = ffma2(h23.x, Wp[k][2], a2);                                  \
        a3 = ffma2(h23.y, Wp[k][3], a3);                                  \
        a0 = ffma2(h45.x, Wp[k][4], a0);                                  \
        a1 = ffma2(h45.y, Wp[k][5], a1);                                  \
        a2 = ffma2(h67.x, Wp[k][6], a2);                                  \
        a3 = ffma2(h67.y, Wp[k][7], a3);                                  \
        a0 = ffma2(h89.x, Wp[k][8], a0);                                  \
        a1 = ffma2(h89.y, Wp[k][9], a1);                                  \
    } while (0)

__global__ __launch_bounds__(NTHREADS, 1)
void reservoir_kernel(const float* __restrict__ x,
                      const float* __restrict__ Win,
                      const float* __restrict__ Wfb,
                      const float* __restrict__ bias,
                      float* __restrict__ out)
{
    extern __shared__ float sm[];
    float* Hring = sm;                     // [RING][RDIM]   = 13520 f
    float* xs    = Hring + RING * RDIM;    // [SEQ]          = 8192 f
    float* part  = xs + SEQ;               // [2][NTHREADS]  = 640 f (double-buffered)

    const int b   = blockIdx.x;
    const int tid = threadIdx.x;
    const int i   = tid % RDIM;   // output index (warps mostly uniform jh)
    const int jh  = tid / RDIM;   // j-quarter 0..3

    // Zero the state ring (pre-t=0 states are zero)
    for (int idx = tid; idx < RING * RDIM; idx += NTHREADS) Hring[idx] = 0.0f;

    // Stage this batch's input sequence (INPUT_DIM == 1)
    const float* xb = x + (size_t)b * SEQ;
    for (int idx = tid; idx < SEQ; idx += NTHREADS) xs[idx] = xb[idx];

    // W_fb slice in registers as f32x2 pairs:
    // feedback[i] = sum_k sum_j delayed[k][j] * Wfb[k][i][j]
    u64 Wp[NTAPS][NPAIR];
#pragma unroll
    for (int k = 0; k < NTAPS; k++) {
        const float* wrow = Wfb + ((size_t)k * RDIM + i) * RDIM + jh * JSLICE;
#pragma unroll
        for (int p = 0; p < NPAIR; p++) {
            unsigned lo = __float_as_uint(wrow[2 * p]);
            unsigned hi = __float_as_uint(wrow[2 * p + 1]);
            Wp[k][p] = ((u64)hi << 32) | (u64)lo;
        }
    }

    float win_i = 0.0f, bias_i = 0.0f, h_i = 0.0f;
    if (tid < RDIM) { win_i = Win[tid]; bias_i = bias[tid]; }

    float* outb = out + (size_t)b * SEQ * RDIM;
    const float* hbase = Hring + jh * JSLICE;

    // Ring slots at t=0: write w = 0; read r_k = (0 - tau_k) mod 169
    int w  = 0;
    int r0 = RING - 1;    // tau 1
    int r1 = RING - 4;    // tau 4
    int r2 = RING - 24;   // tau 24
    int r3 = RING - 96;   // tau 96
    int r4 = RING - 168;  // tau 168

    __syncthreads();

#pragma unroll 1
    for (int t = 0; t < SEQ; ++t) {
        u64 a0 = 0ull, a1 = 0ull, a2 = 0ull, a3 = 0ull;

        // ---- P1: old taps (4,24,96,168) — depend on h[t-4] and older.
        // Runs concurrently with the previous step's epilogue (slot w-1 is
        // not read here; all read slots are disjoint from recent writes).
        TAP_ACC(1, hbase + r1 * RDIM);
        TAP_ACC(2, hbase + r2 * RDIM);
        TAP_ACC(3, hbase + r3 * RDIM);
        TAP_ACC(4, hbase + r4 * RDIM);

        // ---- BAR A: h[t-1] (written by epilogue of iter t-1) now visible.
        __syncthreads();

        // ---- P2: tap 1 — the only work that needs h[t-1].
        TAP_ACC(0, hbase + r0 * RDIM);

        float2 f0 = unpack2(a0);
        float2 f1 = unpack2(a1);
        float2 f2 = unpack2(a2);
        float2 f3 = unpack2(a3);
        part[(t & 1) * NTHREADS + tid] =
            ((f0.x + f0.y) + (f1.x + f1.y)) + ((f2.x + f2.y) + (f3.x + f3.y));

        // ---- BAR B: partials visible.
        __syncthreads();

        // ---- Epilogue (80 threads): reduce, tanh, state update, publish.
        // Other warps fall through to the next iteration's P1 immediately.
        if (tid < RDIM) {
            const float* pb = part + (t & 1) * NTHREADS;
            float f = (pb[tid] + pb[tid + RDIM]) +
                      (pb[tid + 2 * RDIM] + pb[tid + 3 * RDIM]);
            float val = fmaf(xs[t], win_i, f + bias_i);
            h_i = 0.7f * h_i + 0.3f * fast_tanh(val);
            Hring[w * RDIM + tid] = h_i;
            outb[(size_t)t * RDIM + tid] = h_i;
        }

        // advance ring offsets (mod 169)
        ++w;  if (w  == RING) w  = 0;
        ++r0; if (r0 == RING) r0 = 0;
        ++r1; if (r1 == RING) r1 = 0;
        ++r2; if (r2 == RING) r2 = 0;
        ++r3; if (r3 == RING) r3 = 0;
        ++r4; if (r4 == RING) r4 = 0;
    }
}

extern "C" void kernel_launch(void* const* d_in, const int* in_sizes, int n_in,
                              void* d_out, int out_size)
{
    const float* x    = (const float*)d_in[0];  // [64, 8192, 1]
    const float* Win  = (const float*)d_in[1];  // [80, 1]
    const float* Wfb  = (const float*)d_in[2];  // [5, 80, 80]
    const float* bias = (const float*)d_in[3];  // [80]
    float* out = (float*)d_out;                 // [64, 8192, 80]

    const int smem_bytes = (RING * RDIM + SEQ + 2 * NTHREADS) * sizeof(float);
    cudaFuncSetAttribute(reservoir_kernel,
                         cudaFuncAttributeMaxDynamicSharedMemorySize, smem_bytes);

    reservoir_kernel<<<BATCH, NTHREADS, smem_bytes>>>(x, Win, Wfb, bias, out);
}